// round 1
// baseline (speedup 1.0000x reference)
#include <cuda_runtime.h>

// Problem constants
#define BB  4
#define LL  256
#define EE  128
#define HH  8
#define DD  16
#define NUU 512
#define BLr (BB*LL)   // 1024
#define TLu 8         // query tile for uu2du

// ---------------- scratch (device globals; no allocation) ----------------
__device__ float g_qu[BLr*EE];
__device__ float g_qt[BLr*EE];
__device__ float g_qd[BLr*EE];
__device__ float g_kd[BLr*EE];
__device__ float g_vd[BLr*EE];
__device__ float g_kt[BLr*EE];
__device__ float g_vt[BLr*EE];
__device__ float g_K0[BB*NUU*EE];
__device__ float g_V0[BB*NUU*EE];
__device__ float g_CIT[BB*512*512];     // transposed CIMat: [b][j][n]
__device__ float g_att_u[BLr*EE];
__device__ float g_att_t[BLr*EE];
__device__ float g_att_d[BLr*EE];
__device__ float g_Mu[EE*EE];
__device__ float g_Mt[EE*EE];
__device__ float g_Md[EE*EE];
__device__ float g_cb[EE];
__device__ float g_y[BLr*EE];
__device__ float g_mean[EE];
__device__ float g_istd[EE];

// ---------------- fused projection GEMM: C[M,128] = A @ W^T + bias --------
// W element addressed as W[n*wsn + k*wsk] so both row-major W[N,K] (wsk=1)
// and "A@B" style (wsn=1, wsk=128) are supported.
__global__ __launch_bounds__(256) void proj_all_kernel(
    const float* __restrict__ DU, const float* __restrict__ TA, const float* __restrict__ UU,
    const float* __restrict__ uu_w, const float* __restrict__ uu_b,
    const float* __restrict__ ta_w, const float* __restrict__ ta_b,
    const float* __restrict__ du_w, const float* __restrict__ du_b,
    const float* __restrict__ uu_ow, const float* __restrict__ ta_ow, const float* __restrict__ du_ow,
    const float* __restrict__ dim_w)
{
    __shared__ float As[32*33];
    __shared__ float Ws[32*132];
    const float* A; const float* W; const float* bias; float* C;
    int lda, M, K, wsn, wsk;
    switch (blockIdx.y) {
      case 0:  A=DU;        lda=128; M=1024; K=128; W=uu_w;       wsn=128; wsk=1;  bias=uu_b;     C=g_qu; break;
      case 1:  A=DU;        lda=128; M=1024; K=128; W=ta_w;       wsn=128; wsk=1;  bias=ta_b;     C=g_qt; break;
      case 2:  A=DU;        lda=128; M=1024; K=128; W=du_w;       wsn=128; wsk=1;  bias=du_b;     C=g_qd; break;
      case 3:  A=DU;        lda=128; M=1024; K=128; W=du_w+16384; wsn=128; wsk=1;  bias=du_b+128; C=g_kd; break;
      case 4:  A=DU;        lda=128; M=1024; K=128; W=du_w+32768; wsn=128; wsk=1;  bias=du_b+256; C=g_vd; break;
      case 5:  A=TA;        lda=128; M=1024; K=128; W=ta_w+16384; wsn=128; wsk=1;  bias=ta_b+128; C=g_kt; break;
      case 6:  A=TA;        lda=128; M=1024; K=128; W=ta_w+32768; wsn=128; wsk=1;  bias=ta_b+256; C=g_vt; break;
      case 7:  A=UU;        lda=126; M=2048; K=126; W=uu_w+16384; wsn=128; wsk=1;  bias=uu_b+128; C=g_K0; break;
      case 8:  A=UU;        lda=126; M=2048; K=126; W=uu_w+32768; wsn=128; wsk=1;  bias=uu_b+256; C=g_V0; break;
      case 9:  A=dim_w;     lda=384; M=128;  K=128; W=uu_ow;      wsn=1;   wsk=128; bias=nullptr; C=g_Mu; break;
      case 10: A=dim_w+128; lda=384; M=128;  K=128; W=ta_ow;      wsn=1;   wsk=128; bias=nullptr; C=g_Mt; break;
      default: A=dim_w+256; lda=384; M=128;  K=128; W=du_ow;      wsn=1;   wsk=128; bias=nullptr; C=g_Md; break;
    }
    int row0 = blockIdx.x * 32;
    if (row0 >= M) return;
    int t  = threadIdx.x;
    int ti = t >> 5, tj = t & 31;
    float acc[4][4] = {};
    for (int kc = 0; kc < K; kc += 32) {
        #pragma unroll
        for (int i = 0; i < 4; i++) {
            int idx = t + i*256;
            int r = idx >> 5, c = idx & 31;
            float v = 0.f;
            if (kc + c < K) v = A[(row0 + r) * lda + kc + c];
            As[r*33 + c] = v;
        }
        #pragma unroll
        for (int i = 0; i < 16; i++) {
            int idx = t + i*256;
            int col, kk;
            if (wsk == 1) { col = idx >> 5;  kk = idx & 31; }
            else          { col = idx & 127; kk = idx >> 7; }
            float v = 0.f;
            if (kc + kk < K) v = W[col * wsn + (kc + kk) * wsk];
            Ws[kk*132 + col] = v;
        }
        __syncthreads();
        #pragma unroll
        for (int kk = 0; kk < 32; kk++) {
            float4 w4 = *(const float4*)&Ws[kk*132 + (tj<<2)];
            #pragma unroll
            for (int i = 0; i < 4; i++) {
                float a = As[(ti*4 + i)*33 + kk];
                acc[i][0] += a*w4.x; acc[i][1] += a*w4.y;
                acc[i][2] += a*w4.z; acc[i][3] += a*w4.w;
            }
        }
        __syncthreads();
    }
    #pragma unroll
    for (int i = 0; i < 4; i++) {
        int r = row0 + ti*4 + i;
        float4 o;
        o.x = acc[i][0]; o.y = acc[i][1]; o.z = acc[i][2]; o.w = acc[i][3];
        if (bias) {
            o.x += bias[(tj<<2)];   o.y += bias[(tj<<2)+1];
            o.z += bias[(tj<<2)+2]; o.w += bias[(tj<<2)+3];
        }
        *(float4*)&C[r*128 + (tj<<2)] = o;
    }
}

// ---------------- CIMat transpose: CIT[b][j][n] = CI[b][n][j] -------------
__global__ void transpose_ci_kernel(const float* __restrict__ CI) {
    __shared__ float s[32][33];
    int b  = blockIdx.z;
    int n0 = blockIdx.x << 5, j0 = blockIdx.y << 5;
    int tx = threadIdx.x, ty = threadIdx.y;
    #pragma unroll
    for (int k = 0; k < 32; k += 8)
        s[ty + k][tx] = CI[((b << 9) + n0 + ty + k) * 512 + j0 + tx];
    __syncthreads();
    #pragma unroll
    for (int k = 0; k < 32; k += 8)
        g_CIT[((b << 9) + j0 + ty + k) * 512 + n0 + tx] = s[tx][ty + k];
}

// ---------------- combined bias: cb = dim_b + dim_w @ concat(out_b) -------
__global__ void cb_kernel(const float* __restrict__ dim_w, const float* __restrict__ dim_b,
                          const float* __restrict__ uob, const float* __restrict__ tob,
                          const float* __restrict__ dob) {
    int e = threadIdx.x;
    float s = dim_b[e];
    for (int g = 0; g < 128; g++) {
        s += dim_w[e*384 + g]       * uob[g];
        s += dim_w[e*384 + 128 + g] * tob[g];
        s += dim_w[e*384 + 256 + g] * dob[g];
    }
    g_cb[e] = s;
}

// ---------------- uu2du attention with rank-2 key/value update -----------
__global__ __launch_bounds__(256) void uu2du_kernel(const float* __restrict__ uu_w) {
    extern __shared__ float sm[];
    float* sq   = sm;            // TLu*128 = 1024
    float* sci0 = sq   + 1024;   // TLu*512 = 4096
    float* sci1 = sci0 + 4096;   // 4096
    float* swk6 = sci1 + 4096;   // 128
    float* swk7 = swk6 + 128;    // 128
    float* swv6 = swk7 + 128;    // 128
    float* swv7 = swv6 + 128;    // 128
    float* sa   = swv7 + 128;    // 64
    float* sb   = sa   + 64;     // 64
    float* ssum = sb   + 64;     // 64
    float* sc0  = ssum + 64;     // 64
    float* sc1  = sc0  + 64;     // 64
    float* sred = sc1  + 64;     // 1024
    float* ssc  = sred + 1024;   // 64*516 = 33024   (total 44096 floats)

    int b  = blockIdx.y;
    int l0 = blockIdx.x * TLu;
    int t  = threadIdx.x;
    int w = t >> 5, lane = t & 31, h = lane >> 2;

    for (int idx = t; idx < TLu*128; idx += 256)
        sq[idx] = g_qu[((b*LL + l0 + (idx>>7)) << 7) + (idx & 127)];
    for (int idx = t; idx < TLu*512; idx += 256) {
        int l = idx >> 9, n = idx & 511;
        sci0[idx] = g_CIT[((b << 9) + l0 + l) * 512 + n];
        sci1[idx] = g_CIT[((b << 9) + 256 + l0 + l) * 512 + n];
    }
    if (t < 128) {
        swk6[t] = uu_w[(128 + t)*128 + 126];
        swk7[t] = uu_w[(128 + t)*128 + 127];
        swv6[t] = uu_w[(256 + t)*128 + 126];
        swv7[t] = uu_w[(256 + t)*128 + 127];
    }
    __syncthreads();
    if (t < 64) {
        int l = t >> 3, hh = t & 7;
        float A = 0.f, Bv = 0.f;
        #pragma unroll
        for (int d = 0; d < 16; d++) {
            float qv = sq[(l<<7) + (hh<<4) + d];
            A  += qv * swk6[(hh<<4) + d];
            Bv += qv * swk7[(hh<<4) + d];
        }
        sa[t] = A; sb[t] = Bv;
    }
    __syncthreads();

    // phase 1: scores s[l,h,n] = 0.25*(q_h . K0_h[n] + ci0*a + ci1*b)
    for (int n = w; n < 512; n += 8) {
        float4 k4 = *(const float4*)&g_K0[(((b<<9) + n) << 7) + (lane<<2)];
        #pragma unroll
        for (int l = 0; l < TLu; l++) {
            float4 q4 = *(const float4*)&sq[(l<<7) + (lane<<2)];
            float p = k4.x*q4.x + k4.y*q4.y + k4.z*q4.z + k4.w*q4.w;
            p += __shfl_xor_sync(0xffffffffu, p, 1);
            p += __shfl_xor_sync(0xffffffffu, p, 2);
            if ((lane & 3) == 0) {
                int pr = (l<<3) + h;
                float s = (p + sci0[(l<<9)+n]*sa[pr] + sci1[(l<<9)+n]*sb[pr]) * 0.25f;
                ssc[pr*516 + n] = s;
            }
        }
    }
    __syncthreads();

    // phase 2: unnormalized softmax + ci-weighted prob sums
    for (int pr = w; pr < 64; pr += 8) {
        int l = pr >> 3;
        float* row = &ssc[pr*516];
        float m = -1e30f;
        for (int n = lane; n < 512; n += 32) m = fmaxf(m, row[n]);
        #pragma unroll
        for (int o = 16; o > 0; o >>= 1) m = fmaxf(m, __shfl_xor_sync(0xffffffffu, m, o));
        float s = 0.f, c0 = 0.f, c1 = 0.f;
        for (int n = lane; n < 512; n += 32) {
            float e = __expf(row[n] - m);
            row[n] = e;
            s  += e;
            c0 += e * sci0[(l<<9)+n];
            c1 += e * sci1[(l<<9)+n];
        }
        #pragma unroll
        for (int o = 16; o > 0; o >>= 1) {
            s  += __shfl_xor_sync(0xffffffffu, s,  o);
            c0 += __shfl_xor_sync(0xffffffffu, c0, o);
            c1 += __shfl_xor_sync(0xffffffffu, c1, o);
        }
        if (lane == 0) { ssum[pr] = s; sc0[pr] = c0; sc1[pr] = c1; }
    }
    __syncthreads();

    // phase 3: V accumulation + rank-2 V correction, normalize
    float4 acc[TLu];
    #pragma unroll
    for (int l = 0; l < TLu; l++) acc[l] = make_float4(0.f, 0.f, 0.f, 0.f);
    for (int n = w; n < 512; n += 8) {
        float4 v4 = *(const float4*)&g_V0[(((b<<9) + n) << 7) + (lane<<2)];
        #pragma unroll
        for (int l = 0; l < TLu; l++) {
            float p = ssc[((l<<3) + h)*516 + n];
            acc[l].x += p*v4.x; acc[l].y += p*v4.y; acc[l].z += p*v4.z; acc[l].w += p*v4.w;
        }
    }
    for (int l = 0; l < TLu; l++) {
        *(float4*)&sred[(w<<7) + (lane<<2)] = acc[l];
        __syncthreads();
        if (t < 128) {
            float o = 0.f;
            #pragma unroll
            for (int ww = 0; ww < 8; ww++) o += sred[(ww<<7) + t];
            int pr = (l<<3) + (t>>4);
            o += sc0[pr]*swv6[t] + sc1[pr]*swv7[t];
            o /= ssum[pr];
            g_att_u[((b*LL + l0 + l) << 7) + t] = o;
        }
        __syncthreads();
    }
}

// ---------------- standard MHA for ta2du / du2du --------------------------
__global__ __launch_bounds__(256) void mha_kernel() {
    extern __shared__ float sm[];
    float* sk   = sm;            // 256*17 = 4352
    float* sv   = sk   + 4352;   // 4352
    float* sq   = sv   + 4352;   // 512
    float* sinv = sq   + 512;    // 32
    float* ssc  = sinv + 32;     // 32*257 = 8224   (total 17472 floats)

    int which = blockIdx.z & 1;
    int b = blockIdx.z >> 1;
    int h = blockIdx.y;
    int q0 = blockIdx.x << 5;
    const float* Q = which ? g_qd : g_qt;
    const float* K = which ? g_kd : g_kt;
    const float* V = which ? g_vd : g_vt;
    float* O       = which ? g_att_d : g_att_t;
    int t = threadIdx.x;

    for (int idx = t; idx < 4096; idx += 256) {
        int j = idx >> 4, d = idx & 15;
        sk[j*17 + d] = K[((b<<8) + j) * 128 + (h<<4) + d];
        sv[j*17 + d] = V[((b<<8) + j) * 128 + (h<<4) + d];
    }
    for (int idx = t; idx < 512; idx += 256) {
        int i = idx >> 4, d = idx & 15;
        sq[idx] = Q[((b<<8) + q0 + i) * 128 + (h<<4) + d];
    }
    __syncthreads();

    // scores: thread t owns key column j = t
    {
        float kr[16];
        #pragma unroll
        for (int d = 0; d < 16; d++) kr[d] = sk[t*17 + d];
        for (int i = 0; i < 32; i++) {
            float s = 0.f;
            #pragma unroll
            for (int d = 0; d < 16; d++) s += sq[(i<<4) + d] * kr[d];
            ssc[i*257 + t] = s * 0.25f;
        }
    }
    __syncthreads();

    // softmax rows (unnormalized, keep 1/sum)
    {
        int w = t >> 5, lane = t & 31;
        for (int r = 0; r < 4; r++) {
            int i = (w<<2) + r;
            float* row = &ssc[i*257];
            float m = -1e30f;
            #pragma unroll
            for (int j = lane; j < 256; j += 32) m = fmaxf(m, row[j]);
            #pragma unroll
            for (int o = 16; o > 0; o >>= 1) m = fmaxf(m, __shfl_xor_sync(0xffffffffu, m, o));
            float s = 0.f;
            #pragma unroll
            for (int j = lane; j < 256; j += 32) { float e = __expf(row[j]-m); row[j] = e; s += e; }
            #pragma unroll
            for (int o = 16; o > 0; o >>= 1) s += __shfl_xor_sync(0xffffffffu, s, o);
            if (lane == 0) sinv[i] = 1.f / s;
        }
    }
    __syncthreads();

    // output: thread handles (query i, two dims)
    {
        int i = t >> 3, g = t & 7, d0 = g << 1;
        float a0 = 0.f, a1 = 0.f;
        for (int j = 0; j < 256; j++) {
            float e = ssc[i*257 + j];
            a0 += e * sv[j*17 + d0];
            a1 += e * sv[j*17 + d0 + 1];
        }
        float inv = sinv[i];
        int o = ((b<<8) + q0 + i) * 128 + (h<<4) + d0;
        O[o]   = a0 * inv;
        O[o+1] = a1 * inv;
    }
}

// ---------------- final fused GEMM: y = sum att_x @ M_x^T + cb ------------
__global__ __launch_bounds__(256) void final_gemm_kernel() {
    __shared__ float As[32*33];
    __shared__ float Ws[32*132];
    int row0 = blockIdx.x << 5;
    int t = threadIdx.x;
    int ti = t >> 5, tj = t & 31;
    float acc[4][4] = {};
    const float* Asrc[3] = { g_att_u, g_att_t, g_att_d };
    const float* Wsrc[3] = { g_Mu, g_Mt, g_Md };
    for (int s = 0; s < 3; s++) {
        const float* A = Asrc[s];
        const float* W = Wsrc[s];
        for (int kc = 0; kc < 128; kc += 32) {
            #pragma unroll
            for (int i = 0; i < 4; i++) {
                int idx = t + i*256; int r = idx>>5, c = idx&31;
                As[r*33 + c] = A[(row0 + r)*128 + kc + c];
            }
            #pragma unroll
            for (int i = 0; i < 16; i++) {
                int idx = t + i*256; int col = idx>>5, kk = idx&31;
                Ws[kk*132 + col] = W[col*128 + kc + kk];
            }
            __syncthreads();
            #pragma unroll
            for (int kk = 0; kk < 32; kk++) {
                float4 w4 = *(const float4*)&Ws[kk*132 + (tj<<2)];
                #pragma unroll
                for (int i = 0; i < 4; i++) {
                    float a = As[(ti*4+i)*33 + kk];
                    acc[i][0] += a*w4.x; acc[i][1] += a*w4.y;
                    acc[i][2] += a*w4.z; acc[i][3] += a*w4.w;
                }
            }
            __syncthreads();
        }
    }
    #pragma unroll
    for (int i = 0; i < 4; i++) {
        int r = row0 + ti*4 + i;
        float4 o;
        o.x = acc[i][0] + g_cb[(tj<<2)];
        o.y = acc[i][1] + g_cb[(tj<<2)+1];
        o.z = acc[i][2] + g_cb[(tj<<2)+2];
        o.w = acc[i][3] + g_cb[(tj<<2)+3];
        *(float4*)&g_y[r*128 + (tj<<2)] = o;
    }
}

// ---------------- BatchNorm statistics (two-pass per channel) -------------
__global__ __launch_bounds__(256) void bn_stats_kernel() {
    __shared__ float red[256];
    int c = blockIdx.x, t = threadIdx.x;
    float s = 0.f;
    for (int i = t; i < 1024; i += 256) s += g_y[(i<<7) + c];
    red[t] = s; __syncthreads();
    for (int o = 128; o > 0; o >>= 1) { if (t < o) red[t] += red[t+o]; __syncthreads(); }
    float mean = red[0] * (1.f/1024.f);
    __syncthreads();
    float v = 0.f;
    for (int i = t; i < 1024; i += 256) { float d = g_y[(i<<7)+c] - mean; v += d*d; }
    red[t] = v; __syncthreads();
    for (int o = 128; o > 0; o >>= 1) { if (t < o) red[t] += red[t+o]; __syncthreads(); }
    if (t == 0) { g_mean[c] = mean; g_istd[c] = rsqrtf(red[0]*(1.f/1024.f) + 1e-5f); }
}

// ---------------- BN apply + ReLU ----------------------------------------
__global__ void bn_apply_kernel(const float* __restrict__ gamma, const float* __restrict__ beta,
                                float* __restrict__ out) {
    int idx = blockIdx.x*512 + threadIdx.x;
    int c = idx & 127;
    float v = (g_y[idx] - g_mean[c]) * g_istd[c] * gamma[c] + beta[c];
    out[idx] = fmaxf(v, 0.f);
}

// ---------------- host launch --------------------------------------------
extern "C" void kernel_launch(void* const* d_in, const int* in_sizes, int n_in,
                              void* d_out, int out_size) {
    const float* UU    = (const float*)d_in[0];
    const float* DU    = (const float*)d_in[1];
    const float* TA    = (const float*)d_in[2];
    const float* CI    = (const float*)d_in[3];
    const float* uu_w  = (const float*)d_in[4];
    const float* uu_b  = (const float*)d_in[5];
    const float* uu_ow = (const float*)d_in[6];
    const float* uu_ob = (const float*)d_in[7];
    const float* ta_w  = (const float*)d_in[8];
    const float* ta_b  = (const float*)d_in[9];
    const float* ta_ow = (const float*)d_in[10];
    const float* ta_ob = (const float*)d_in[11];
    const float* du_w  = (const float*)d_in[12];
    const float* du_b  = (const float*)d_in[13];
    const float* du_ow = (const float*)d_in[14];
    const float* du_ob = (const float*)d_in[15];
    const float* dim_w = (const float*)d_in[16];
    const float* dim_b = (const float*)d_in[17];
    const float* gamma = (const float*)d_in[18];
    const float* beta  = (const float*)d_in[19];
    float* out = (float*)d_out;

    cudaFuncSetAttribute(uu2du_kernel, cudaFuncAttributeMaxDynamicSharedMemorySize, 44096*4);
    cudaFuncSetAttribute(mha_kernel,   cudaFuncAttributeMaxDynamicSharedMemorySize, 17472*4);

    proj_all_kernel<<<dim3(64,12), 256>>>(DU, TA, UU, uu_w, uu_b, ta_w, ta_b,
                                          du_w, du_b, uu_ow, ta_ow, du_ow, dim_w);
    transpose_ci_kernel<<<dim3(16,16,4), dim3(32,8)>>>(CI);
    cb_kernel<<<1,128>>>(dim_w, dim_b, uu_ob, ta_ob, du_ob);
    uu2du_kernel<<<dim3(32,4), 256, 44096*4>>>(uu_w);
    mha_kernel<<<dim3(8,8,8), 256, 17472*4>>>();
    final_gemm_kernel<<<32,256>>>();
    bn_stats_kernel<<<128,256>>>();
    bn_apply_kernel<<<256,512>>>(gamma, beta, out);
}

// round 3
// speedup vs baseline: 1.2907x; 1.2907x over previous
#include <cuda_runtime.h>

// Problem constants
#define BB  4
#define LL  256
#define EE  128
#define HH  8
#define DD  16
#define NUU 512
#define BLr (BB*LL)   // 1024
#define TLu 4         // query tile for uu2du

// ---------------- scratch (device globals; no allocation) ----------------
__device__ float g_qu[BLr*EE];
__device__ float g_qt[BLr*EE];
__device__ float g_qd[BLr*EE];
__device__ float g_kd[BLr*EE];
__device__ float g_vd[BLr*EE];
__device__ float g_kt[BLr*EE];
__device__ float g_vt[BLr*EE];
__device__ float g_K0T[BB*HH*DD*NUU];   // [b][h][d][n]
__device__ float g_V0T[BB*HH*DD*NUU];   // [b][h][d][n]
__device__ float g_CIT[BB*512*512];     // transposed CIMat: [b][j][n]
__device__ float g_att_u[BLr*EE];
__device__ float g_att_t[BLr*EE];
__device__ float g_att_d[BLr*EE];
__device__ float g_Mu[EE*EE];
__device__ float g_Mt[EE*EE];
__device__ float g_Md[EE*EE];
__device__ float g_cb[EE];
__device__ float g_y[BLr*EE];
__device__ float g_mean[EE];
__device__ float g_istd[EE];

// ---------------- fused projection GEMM: C[M,128] = A @ W^T + bias --------
// W element addressed as W[n*wsn + k*wsk]. Slots 7/8 store transposed into
// [b][h][d][n] layout (tstore).
__global__ __launch_bounds__(256) void proj_all_kernel(
    const float* __restrict__ DU, const float* __restrict__ TA, const float* __restrict__ UU,
    const float* __restrict__ uu_w, const float* __restrict__ uu_b,
    const float* __restrict__ ta_w, const float* __restrict__ ta_b,
    const float* __restrict__ du_w, const float* __restrict__ du_b,
    const float* __restrict__ uu_ow, const float* __restrict__ ta_ow, const float* __restrict__ du_ow,
    const float* __restrict__ dim_w)
{
    __shared__ float As[32*33];
    __shared__ float Ws[32*132];
    const float* A; const float* W; const float* bias; float* C;
    int lda, M, K, wsn, wsk; bool tstore = false;
    switch (blockIdx.y) {
      case 0:  A=DU;        lda=128; M=1024; K=128; W=uu_w;       wsn=128; wsk=1;  bias=uu_b;     C=g_qu; break;
      case 1:  A=DU;        lda=128; M=1024; K=128; W=ta_w;       wsn=128; wsk=1;  bias=ta_b;     C=g_qt; break;
      case 2:  A=DU;        lda=128; M=1024; K=128; W=du_w;       wsn=128; wsk=1;  bias=du_b;     C=g_qd; break;
      case 3:  A=DU;        lda=128; M=1024; K=128; W=du_w+16384; wsn=128; wsk=1;  bias=du_b+128; C=g_kd; break;
      case 4:  A=DU;        lda=128; M=1024; K=128; W=du_w+32768; wsn=128; wsk=1;  bias=du_b+256; C=g_vd; break;
      case 5:  A=TA;        lda=128; M=1024; K=128; W=ta_w+16384; wsn=128; wsk=1;  bias=ta_b+128; C=g_kt; break;
      case 6:  A=TA;        lda=128; M=1024; K=128; W=ta_w+32768; wsn=128; wsk=1;  bias=ta_b+256; C=g_vt; break;
      case 7:  A=UU;        lda=126; M=2048; K=126; W=uu_w+16384; wsn=128; wsk=1;  bias=uu_b+128; C=g_K0T; tstore=true; break;
      case 8:  A=UU;        lda=126; M=2048; K=126; W=uu_w+32768; wsn=128; wsk=1;  bias=uu_b+256; C=g_V0T; tstore=true; break;
      case 9:  A=dim_w;     lda=384; M=128;  K=128; W=uu_ow;      wsn=1;   wsk=128; bias=nullptr; C=g_Mu; break;
      case 10: A=dim_w+128; lda=384; M=128;  K=128; W=ta_ow;      wsn=1;   wsk=128; bias=nullptr; C=g_Mt; break;
      default: A=dim_w+256; lda=384; M=128;  K=128; W=du_ow;      wsn=1;   wsk=128; bias=nullptr; C=g_Md; break;
    }
    int row0 = blockIdx.x * 32;
    if (row0 >= M) return;
    int t  = threadIdx.x;
    int ti = t >> 5, tj = t & 31;
    float acc[4][4] = {};
    for (int kc = 0; kc < K; kc += 32) {
        #pragma unroll
        for (int i = 0; i < 4; i++) {
            int idx = t + i*256;
            int r = idx >> 5, c = idx & 31;
            float v = 0.f;
            if (kc + c < K) v = A[(row0 + r) * lda + kc + c];
            As[r*33 + c] = v;
        }
        #pragma unroll
        for (int i = 0; i < 16; i++) {
            int idx = t + i*256;
            int col, kk;
            if (wsk == 1) { col = idx >> 5;  kk = idx & 31; }
            else          { col = idx & 127; kk = idx >> 7; }
            float v = 0.f;
            if (kc + kk < K) v = W[col * wsn + (kc + kk) * wsk];
            Ws[kk*132 + col] = v;
        }
        __syncthreads();
        #pragma unroll
        for (int kk = 0; kk < 32; kk++) {
            float4 w4 = *(const float4*)&Ws[kk*132 + (tj<<2)];
            #pragma unroll
            for (int i = 0; i < 4; i++) {
                float a = As[(ti*4 + i)*33 + kk];
                acc[i][0] += a*w4.x; acc[i][1] += a*w4.y;
                acc[i][2] += a*w4.z; acc[i][3] += a*w4.w;
            }
        }
        __syncthreads();
    }
    #pragma unroll
    for (int i = 0; i < 4; i++) {
        int r = row0 + ti*4 + i;
        float o[4];
        #pragma unroll
        for (int j = 0; j < 4; j++) {
            o[j] = acc[i][j];
            if (bias) o[j] += bias[(tj<<2)+j];
        }
        if (tstore) {
            int b = r >> 9, n = r & 511;
            #pragma unroll
            for (int j = 0; j < 4; j++) {
                int e = (tj<<2)+j;            // e = h*16 + d
                C[((b<<7) + e)*512 + n] = o[j];   // ((b*8+h)*16+d)*512+n
            }
        } else {
            float4 v; v.x=o[0]; v.y=o[1]; v.z=o[2]; v.w=o[3];
            *(float4*)&C[r*128 + (tj<<2)] = v;
        }
    }
}

// ---------------- CIMat transpose: CIT[b][j][n] = CI[b][n][j] -------------
__global__ void transpose_ci_kernel(const float* __restrict__ CI) {
    __shared__ float s[32][33];
    int b  = blockIdx.z;
    int n0 = blockIdx.x << 5, j0 = blockIdx.y << 5;
    int tx = threadIdx.x, ty = threadIdx.y;
    #pragma unroll
    for (int k = 0; k < 32; k += 8)
        s[ty + k][tx] = CI[((b << 9) + n0 + ty + k) * 512 + j0 + tx];
    __syncthreads();
    #pragma unroll
    for (int k = 0; k < 32; k += 8)
        g_CIT[((b << 9) + j0 + ty + k) * 512 + n0 + tx] = s[tx][ty + k];
}

// ---------------- combined bias: cb = dim_b + dim_w @ concat(out_b) -------
__global__ void cb_kernel(const float* __restrict__ dim_w, const float* __restrict__ dim_b,
                          const float* __restrict__ uob, const float* __restrict__ tob,
                          const float* __restrict__ dob) {
    int e = threadIdx.x;
    float s = dim_b[e];
    for (int g = 0; g < 128; g++) {
        s += dim_w[e*384 + g]       * uob[g];
        s += dim_w[e*384 + 128 + g] * tob[g];
        s += dim_w[e*384 + 256 + g] * dob[g];
    }
    g_cb[e] = s;
}

// ---------------- uu2du attention: register-resident, warp-per-head -------
// Block = (b, tile of 4 queries). Warp w handles head h=w for all 4 queries.
// Scores kept in registers s[4][16], n = k*32 + lane. Fully coalesced K0T/V0T
// streaming; softmax + rank-2 ci corrections are warp-local.
__global__ __launch_bounds__(256,2) void uu2du_kernel(const float* __restrict__ uu_w) {
    __shared__ float sq[TLu*128];
    __shared__ float sci0[TLu*512];
    __shared__ float sci1[TLu*512];
    __shared__ float swv6[128];
    __shared__ float swv7[128];
    __shared__ float sa[TLu*8];
    __shared__ float sb[TLu*8];

    int b  = blockIdx.y;
    int l0 = blockIdx.x * TLu;
    int t  = threadIdx.x;
    int w = t >> 5, lane = t & 31;
    int h = w;

    for (int idx = t; idx < TLu*128; idx += 256)
        sq[idx] = g_qu[((b*LL + l0 + (idx>>7)) << 7) + (idx & 127)];
    for (int idx = t; idx < TLu*512; idx += 256) {
        int l = idx >> 9, n = idx & 511;
        sci0[idx] = g_CIT[((b << 9) + l0 + l) * 512 + n];
        sci1[idx] = g_CIT[((b << 9) + 256 + l0 + l) * 512 + n];
    }
    if (t < 128) {
        swv6[t] = uu_w[(256 + t)*128 + 126];
        swv7[t] = uu_w[(256 + t)*128 + 127];
    }
    __syncthreads();
    if (t < TLu*8) {
        int l = t >> 3, hh = t & 7;
        float A = 0.f, Bv = 0.f;
        #pragma unroll
        for (int d = 0; d < 16; d++) {
            float qv = sq[(l<<7) + (hh<<4) + d];
            A  += qv * uu_w[(128 + (hh<<4) + d)*128 + 126];
            Bv += qv * uu_w[(128 + (hh<<4) + d)*128 + 127];
        }
        sa[t] = A; sb[t] = Bv;
    }
    __syncthreads();

    // ---------- phase 1: scores ----------
    float s[TLu][16];
    #pragma unroll
    for (int l = 0; l < TLu; l++)
        #pragma unroll
        for (int k = 0; k < 16; k++) s[l][k] = 0.f;

    const float* K0Th = g_K0T + ((b*8 + h) << 4) * 512;   // [d][n]
    for (int d = 0; d < 16; d++) {
        float q0 = sq[0*128 + (h<<4) + d];
        float q1 = sq[1*128 + (h<<4) + d];
        float q2 = sq[2*128 + (h<<4) + d];
        float q3 = sq[3*128 + (h<<4) + d];
        const float* row = K0Th + d*512 + lane;
        #pragma unroll
        for (int k = 0; k < 16; k++) {
            float kv = row[k*32];
            s[0][k] += q0*kv; s[1][k] += q1*kv; s[2][k] += q2*kv; s[3][k] += q3*kv;
        }
    }
    #pragma unroll
    for (int l = 0; l < TLu; l++) {
        float av = sa[(l<<3) + h], bv = sb[(l<<3) + h];
        #pragma unroll
        for (int k = 0; k < 16; k++) {
            int n = k*32 + lane;
            s[l][k] = (s[l][k] + sci0[(l<<9)+n]*av + sci1[(l<<9)+n]*bv) * 0.25f;
        }
    }

    // ---------- phase 2: softmax (warp-local) ----------
    float rsum[TLu], rc0[TLu], rc1[TLu];
    #pragma unroll
    for (int l = 0; l < TLu; l++) {
        float m = -1e30f;
        #pragma unroll
        for (int k = 0; k < 16; k++) m = fmaxf(m, s[l][k]);
        #pragma unroll
        for (int o = 16; o > 0; o >>= 1) m = fmaxf(m, __shfl_xor_sync(0xffffffffu, m, o));
        float su = 0.f, c0 = 0.f, c1 = 0.f;
        #pragma unroll
        for (int k = 0; k < 16; k++) {
            float e = __expf(s[l][k] - m);
            s[l][k] = e;
            int n = k*32 + lane;
            su += e;
            c0 += e * sci0[(l<<9)+n];
            c1 += e * sci1[(l<<9)+n];
        }
        #pragma unroll
        for (int o = 16; o > 0; o >>= 1) {
            su += __shfl_xor_sync(0xffffffffu, su, o);
            c0 += __shfl_xor_sync(0xffffffffu, c0, o);
            c1 += __shfl_xor_sync(0xffffffffu, c1, o);
        }
        rsum[l] = su; rc0[l] = c0; rc1[l] = c1;
    }

    // ---------- phase 3: P @ V0 (two d-halves to bound registers) ----------
    const float* V0Th = g_V0T + ((b*8 + h) << 4) * 512;
    #pragma unroll
    for (int half = 0; half < 2; half++) {
        float acc[TLu][8];
        #pragma unroll
        for (int l = 0; l < TLu; l++)
            #pragma unroll
            for (int dd = 0; dd < 8; dd++) acc[l][dd] = 0.f;
        for (int dd = 0; dd < 8; dd++) {
            const float* row = V0Th + (half*8 + dd)*512 + lane;
            #pragma unroll
            for (int k = 0; k < 16; k++) {
                float v = row[k*32];
                acc[0][dd] += s[0][k]*v; acc[1][dd] += s[1][k]*v;
                acc[2][dd] += s[2][k]*v; acc[3][dd] += s[3][k]*v;
            }
        }
        #pragma unroll
        for (int o = 16; o > 0; o >>= 1)
            #pragma unroll
            for (int l = 0; l < TLu; l++)
                #pragma unroll
                for (int dd = 0; dd < 8; dd++)
                    acc[l][dd] += __shfl_xor_sync(0xffffffffu, acc[l][dd], o);
        if (lane < 8) {
            int d = half*8 + lane;
            #pragma unroll
            for (int l = 0; l < TLu; l++) {
                float o = acc[l][lane] + rc0[l]*swv6[(h<<4)+d] + rc1[l]*swv7[(h<<4)+d];
                o /= rsum[l];
                g_att_u[((b*LL + l0 + l) << 7) + (h<<4) + d] = o;
            }
        }
    }
}

// ---------------- standard MHA for ta2du / du2du --------------------------
__global__ __launch_bounds__(256) void mha_kernel() {
    extern __shared__ float sm[];
    float* sk   = sm;            // 256*17 = 4352
    float* sv   = sk   + 4352;   // 4352
    float* sq   = sv   + 4352;   // 512
    float* sinv = sq   + 512;    // 32
    float* ssc  = sinv + 32;     // 32*257 = 8224   (total 17472 floats)

    int which = blockIdx.z & 1;
    int b = blockIdx.z >> 1;
    int h = blockIdx.y;
    int q0 = blockIdx.x << 5;
    const float* Q = which ? g_qd : g_qt;
    const float* K = which ? g_kd : g_kt;
    const float* V = which ? g_vd : g_vt;
    float* O       = which ? g_att_d : g_att_t;
    int t = threadIdx.x;

    for (int idx = t; idx < 4096; idx += 256) {
        int j = idx >> 4, d = idx & 15;
        sk[j*17 + d] = K[((b<<8) + j) * 128 + (h<<4) + d];
        sv[j*17 + d] = V[((b<<8) + j) * 128 + (h<<4) + d];
    }
    for (int idx = t; idx < 512; idx += 256) {
        int i = idx >> 4, d = idx & 15;
        sq[idx] = Q[((b<<8) + q0 + i) * 128 + (h<<4) + d];
    }
    __syncthreads();

    {
        float kr[16];
        #pragma unroll
        for (int d = 0; d < 16; d++) kr[d] = sk[t*17 + d];
        for (int i = 0; i < 32; i++) {
            float s = 0.f;
            #pragma unroll
            for (int d = 0; d < 16; d++) s += sq[(i<<4) + d] * kr[d];
            ssc[i*257 + t] = s * 0.25f;
        }
    }
    __syncthreads();

    {
        int w = t >> 5, lane = t & 31;
        for (int r = 0; r < 4; r++) {
            int i = (w<<2) + r;
            float* row = &ssc[i*257];
            float m = -1e30f;
            #pragma unroll
            for (int j = lane; j < 256; j += 32) m = fmaxf(m, row[j]);
            #pragma unroll
            for (int o = 16; o > 0; o >>= 1) m = fmaxf(m, __shfl_xor_sync(0xffffffffu, m, o));
            float s = 0.f;
            #pragma unroll
            for (int j = lane; j < 256; j += 32) { float e = __expf(row[j]-m); row[j] = e; s += e; }
            #pragma unroll
            for (int o = 16; o > 0; o >>= 1) s += __shfl_xor_sync(0xffffffffu, s, o);
            if (lane == 0) sinv[i] = 1.f / s;
        }
    }
    __syncthreads();

    {
        int i = t >> 3, g = t & 7, d0 = g << 1;
        float a0 = 0.f, a1 = 0.f;
        for (int j = 0; j < 256; j++) {
            float e = ssc[i*257 + j];
            a0 += e * sv[j*17 + d0];
            a1 += e * sv[j*17 + d0 + 1];
        }
        float inv = sinv[i];
        int o = ((b<<8) + q0 + i) * 128 + (h<<4) + d0;
        O[o]   = a0 * inv;
        O[o+1] = a1 * inv;
    }
}

// ---------------- final fused GEMM: y = sum att_x @ M_x^T + cb ------------
__global__ __launch_bounds__(256) void final_gemm_kernel() {
    __shared__ float As[32*33];
    __shared__ float Ws[32*132];
    int row0 = blockIdx.x << 5;
    int t = threadIdx.x;
    int ti = t >> 5, tj = t & 31;
    float acc[4][4] = {};
    const float* Asrc[3] = { g_att_u, g_att_t, g_att_d };
    const float* Wsrc[3] = { g_Mu, g_Mt, g_Md };
    for (int s = 0; s < 3; s++) {
        const float* A = Asrc[s];
        const float* W = Wsrc[s];
        for (int kc = 0; kc < 128; kc += 32) {
            #pragma unroll
            for (int i = 0; i < 4; i++) {
                int idx = t + i*256; int r = idx>>5, c = idx&31;
                As[r*33 + c] = A[(row0 + r)*128 + kc + c];
            }
            #pragma unroll
            for (int i = 0; i < 16; i++) {
                int idx = t + i*256; int col = idx>>5, kk = idx&31;
                Ws[kk*132 + col] = W[col*128 + kc + kk];
            }
            __syncthreads();
            #pragma unroll
            for (int kk = 0; kk < 32; kk++) {
                float4 w4 = *(const float4*)&Ws[kk*132 + (tj<<2)];
                #pragma unroll
                for (int i = 0; i < 4; i++) {
                    float a = As[(ti*4+i)*33 + kk];
                    acc[i][0] += a*w4.x; acc[i][1] += a*w4.y;
                    acc[i][2] += a*w4.z; acc[i][3] += a*w4.w;
                }
            }
            __syncthreads();
        }
    }
    #pragma unroll
    for (int i = 0; i < 4; i++) {
        int r = row0 + ti*4 + i;
        float4 o;
        o.x = acc[i][0] + g_cb[(tj<<2)];
        o.y = acc[i][1] + g_cb[(tj<<2)+1];
        o.z = acc[i][2] + g_cb[(tj<<2)+2];
        o.w = acc[i][3] + g_cb[(tj<<2)+3];
        *(float4*)&g_y[r*128 + (tj<<2)] = o;
    }
}

// ---------------- BatchNorm statistics (two-pass per channel) -------------
__global__ __launch_bounds__(256) void bn_stats_kernel() {
    __shared__ float red[256];
    int c = blockIdx.x, t = threadIdx.x;
    float s = 0.f;
    for (int i = t; i < 1024; i += 256) s += g_y[(i<<7) + c];
    red[t] = s; __syncthreads();
    for (int o = 128; o > 0; o >>= 1) { if (t < o) red[t] += red[t+o]; __syncthreads(); }
    float mean = red[0] * (1.f/1024.f);
    __syncthreads();
    float v = 0.f;
    for (int i = t; i < 1024; i += 256) { float d = g_y[(i<<7)+c] - mean; v += d*d; }
    red[t] = v; __syncthreads();
    for (int o = 128; o > 0; o >>= 1) { if (t < o) red[t] += red[t+o]; __syncthreads(); }
    if (t == 0) { g_mean[c] = mean; g_istd[c] = rsqrtf(red[0]*(1.f/1024.f) + 1e-5f); }
}

// ---------------- BN apply + ReLU ----------------------------------------
__global__ void bn_apply_kernel(const float* __restrict__ gamma, const float* __restrict__ beta,
                                float* __restrict__ out) {
    int idx = blockIdx.x*512 + threadIdx.x;
    int c = idx & 127;
    float v = (g_y[idx] - g_mean[c]) * g_istd[c] * gamma[c] + beta[c];
    out[idx] = fmaxf(v, 0.f);
}

// ---------------- host launch --------------------------------------------
extern "C" void kernel_launch(void* const* d_in, const int* in_sizes, int n_in,
                              void* d_out, int out_size) {
    const float* UU    = (const float*)d_in[0];
    const float* DU    = (const float*)d_in[1];
    const float* TA    = (const float*)d_in[2];
    const float* CI    = (const float*)d_in[3];
    const float* uu_w  = (const float*)d_in[4];
    const float* uu_b  = (const float*)d_in[5];
    const float* uu_ow = (const float*)d_in[6];
    const float* uu_ob = (const float*)d_in[7];
    const float* ta_w  = (const float*)d_in[8];
    const float* ta_b  = (const float*)d_in[9];
    const float* ta_ow = (const float*)d_in[10];
    const float* ta_ob = (const float*)d_in[11];
    const float* du_w  = (const float*)d_in[12];
    const float* du_b  = (const float*)d_in[13];
    const float* du_ow = (const float*)d_in[14];
    const float* du_ob = (const float*)d_in[15];
    const float* dim_w = (const float*)d_in[16];
    const float* dim_b = (const float*)d_in[17];
    const float* gamma = (const float*)d_in[18];
    const float* beta  = (const float*)d_in[19];
    float* out = (float*)d_out;

    cudaFuncSetAttribute(mha_kernel, cudaFuncAttributeMaxDynamicSharedMemorySize, 17472*4);

    proj_all_kernel<<<dim3(64,12), 256>>>(DU, TA, UU, uu_w, uu_b, ta_w, ta_b,
                                          du_w, du_b, uu_ow, ta_ow, du_ow, dim_w);
    transpose_ci_kernel<<<dim3(16,16,4), dim3(32,8)>>>(CI);
    cb_kernel<<<1,128>>>(dim_w, dim_b, uu_ob, ta_ob, du_ob);
    uu2du_kernel<<<dim3(LL/TLu,4), 256>>>(uu_w);
    mha_kernel<<<dim3(8,8,8), 256, 17472*4>>>();
    final_gemm_kernel<<<32,256>>>();
    bn_stats_kernel<<<128,256>>>();
    bn_apply_kernel<<<256,512>>>(gamma, beta, out);
}

// round 4
// speedup vs baseline: 2.8085x; 2.1759x over previous
#include <cuda_runtime.h>

// Problem constants
#define BB  4
#define LL  256
#define EE  128
#define HH  8
#define DD  16
#define NUU 512
#define BLr 1024
#define TLu 4      // queries per warp (both attention types)

// ---------------- scratch (device globals; no allocation) ----------------
__device__ float g_qu[BLr*EE];
__device__ float g_qt[BLr*EE];
__device__ float g_qd[BLr*EE];
__device__ float g_kdT[BB*HH*DD*LL];    // [b][h][d][l]
__device__ float g_vdT[BB*HH*DD*LL];
__device__ float g_ktT[BB*HH*DD*LL];
__device__ float g_vtT[BB*HH*DD*LL];
__device__ float g_K0T[BB*HH*DD*NUU];   // [b][h][d][n]
__device__ float g_V0T[BB*HH*DD*NUU];
__device__ float g_CIT[BB*512*512];     // [b][j][n]
__device__ float g_att_u[BLr*EE];
__device__ float g_att_t[BLr*EE];
__device__ float g_att_d[BLr*EE];
__device__ float g_Mu[EE*EE];
__device__ float g_Mt[EE*EE];
__device__ float g_Md[EE*EE];
__device__ float g_part[3*BLr*EE];
__device__ float g_y[BLr*EE];

// ---------------- fused projection GEMM: C[M,128] = A @ W^T (+bias) -------
// tshift!=0 -> transposed store into [b][e][n] with n-size (1<<tshift).
__global__ __launch_bounds__(256) void proj_all_kernel(
    const float* __restrict__ DU, const float* __restrict__ TA, const float* __restrict__ UU,
    const float* __restrict__ uu_w, const float* __restrict__ uu_b,
    const float* __restrict__ ta_w, const float* __restrict__ ta_b,
    const float* __restrict__ du_w, const float* __restrict__ du_b,
    const float* __restrict__ uu_ow, const float* __restrict__ ta_ow, const float* __restrict__ du_ow,
    const float* __restrict__ dim_w)
{
    __shared__ float As[64*33];
    __shared__ float Ws[32*132];
    const float* A; const float* W; const float* bias; float* C;
    int lda, M, K, wsn, wsk, tshift = 0;
    switch (blockIdx.y) {
      case 0:  A=DU;        lda=128; M=1024; K=128; W=uu_w;       wsn=128; wsk=1;  bias=uu_b;     C=g_qu;  break;
      case 1:  A=DU;        lda=128; M=1024; K=128; W=ta_w;       wsn=128; wsk=1;  bias=ta_b;     C=g_qt;  break;
      case 2:  A=DU;        lda=128; M=1024; K=128; W=du_w;       wsn=128; wsk=1;  bias=du_b;     C=g_qd;  break;
      case 3:  A=DU;        lda=128; M=1024; K=128; W=du_w+16384; wsn=128; wsk=1;  bias=du_b+128; C=g_kdT; tshift=8; break;
      case 4:  A=DU;        lda=128; M=1024; K=128; W=du_w+32768; wsn=128; wsk=1;  bias=du_b+256; C=g_vdT; tshift=8; break;
      case 5:  A=TA;        lda=128; M=1024; K=128; W=ta_w+16384; wsn=128; wsk=1;  bias=ta_b+128; C=g_ktT; tshift=8; break;
      case 6:  A=TA;        lda=128; M=1024; K=128; W=ta_w+32768; wsn=128; wsk=1;  bias=ta_b+256; C=g_vtT; tshift=8; break;
      case 7:  A=UU;        lda=126; M=2048; K=126; W=uu_w+16384; wsn=128; wsk=1;  bias=uu_b+128; C=g_K0T; tshift=9; break;
      case 8:  A=UU;        lda=126; M=2048; K=126; W=uu_w+32768; wsn=128; wsk=1;  bias=uu_b+256; C=g_V0T; tshift=9; break;
      case 9:  A=dim_w;     lda=384; M=128;  K=128; W=uu_ow;      wsn=1;   wsk=128; bias=nullptr; C=g_Mu;  break;
      case 10: A=dim_w+128; lda=384; M=128;  K=128; W=ta_ow;      wsn=1;   wsk=128; bias=nullptr; C=g_Mt;  break;
      default: A=dim_w+256; lda=384; M=128;  K=128; W=du_ow;      wsn=1;   wsk=128; bias=nullptr; C=g_Md;  break;
    }
    int row0 = blockIdx.x * 64;
    if (row0 >= M) return;
    int t  = threadIdx.x;
    int ti = t >> 5, tj = t & 31;
    float acc[8][4] = {};
    for (int kc = 0; kc < K; kc += 32) {
        #pragma unroll
        for (int i = 0; i < 8; i++) {
            int idx = t + i*256;
            int r = idx >> 5, c = idx & 31;
            float v = 0.f;
            if (kc + c < K) v = A[(row0 + r) * lda + kc + c];
            As[r*33 + c] = v;
        }
        #pragma unroll
        for (int i = 0; i < 16; i++) {
            int idx = t + i*256;
            int col, kk;
            if (wsk == 1) { col = idx >> 5;  kk = idx & 31; }
            else          { col = idx & 127; kk = idx >> 7; }
            float v = 0.f;
            if (kc + kk < K) v = W[col * wsn + (kc + kk) * wsk];
            Ws[kk*132 + col] = v;
        }
        __syncthreads();
        #pragma unroll
        for (int kk = 0; kk < 32; kk++) {
            float4 w4 = *(const float4*)&Ws[kk*132 + (tj<<2)];
            #pragma unroll
            for (int i = 0; i < 8; i++) {
                float a = As[(ti*8 + i)*33 + kk];
                acc[i][0] += a*w4.x; acc[i][1] += a*w4.y;
                acc[i][2] += a*w4.z; acc[i][3] += a*w4.w;
            }
        }
        __syncthreads();
    }
    #pragma unroll
    for (int i = 0; i < 8; i++) {
        int r = row0 + ti*8 + i;
        float o[4];
        #pragma unroll
        for (int j = 0; j < 4; j++) {
            o[j] = acc[i][j];
            if (bias) o[j] += bias[(tj<<2)+j];
        }
        if (tshift) {
            int bb = r >> tshift, n = r & ((1<<tshift)-1);
            #pragma unroll
            for (int j = 0; j < 4; j++) {
                int e = (tj<<2)+j;   // e = h*16+d
                C[(((bb<<7) + e) << tshift) + n] = o[j];
            }
        } else {
            float4 v; v.x=o[0]; v.y=o[1]; v.z=o[2]; v.w=o[3];
            *(float4*)&C[r*128 + (tj<<2)] = v;
        }
    }
}

// ---------------- CIMat transpose: CIT[b][j][n] = CI[b][n][j] -------------
__global__ void transpose_ci_kernel(const float* __restrict__ CI) {
    __shared__ float s[32][33];
    int b  = blockIdx.z;
    int n0 = blockIdx.x << 5, j0 = blockIdx.y << 5;
    int tx = threadIdx.x, ty = threadIdx.y;
    #pragma unroll
    for (int k = 0; k < 32; k += 8)
        s[ty + k][tx] = CI[((b << 9) + n0 + ty + k) * 512 + j0 + tx];
    __syncthreads();
    #pragma unroll
    for (int k = 0; k < 32; k += 8)
        g_CIT[((b << 9) + j0 + ty + k) * 512 + n0 + tx] = s[tx][ty + k];
}

// select a[i] with i = lane (0..7) without dynamic register indexing
__device__ __forceinline__ float pick8(const float* a, int i) {
    float r = a[0];
    #pragma unroll
    for (int k = 1; k < 8; k++) r = (i == k) ? a[k] : r;
    return r;
}

// ---------------- fused attention kernel ----------------------------------
// grid (64, 4, 3), block 256.
// z==0: uu2du. x encodes (ltile = x>>1 -> 8 queries, hg = x&1 -> 4 heads).
//        warp w: head hg*4 + (w>>1), queries (w&1)*4 .. +3 of the 8-tile.
//        Two warps share each head's K/V stream (halves L2 traffic).
// z==1/2: standard MHA (ta / du). x*4 = query tile, warp w = head w.
__global__ __launch_bounds__(256,2) void attn_kernel(const float* __restrict__ uu_w) {
    __shared__ __align__(16) float sq[8*128];
    __shared__ __align__(16) float sci0[8*512];
    __shared__ __align__(16) float sci1[8*512];
    __shared__ float swv6[128], swv7[128], sa[64], sb[64];

    int z = blockIdx.z;
    int b = blockIdx.y;
    int t = threadIdx.x, w = t >> 5, lane = t & 31;

    if (z == 0) {
        int ltile = blockIdx.x >> 1;       // 0..31 -> 8 queries each
        int hg    = blockIdx.x & 1;        // head group
        int l0    = ltile * 8;
        int h     = hg*4 + (w >> 1);       // this warp's head
        int lw    = (w & 1) * 4;           // local query offset (0 or 4)

        const float4* q4p = (const float4*)(g_qu + ((b*LL + l0) << 7));
        for (int i = t; i < 256; i += 256) ((float4*)sq)[i] = q4p[i];
        for (int i = t; i < 1024; i += 256) {
            int l = i >> 7, o = i & 127;
            ((float4*)sci0)[i] = *(const float4*)(g_CIT + ((b<<9) + l0 + l)*512 + (o<<2));
            ((float4*)sci1)[i] = *(const float4*)(g_CIT + ((b<<9) + 256 + l0 + l)*512 + (o<<2));
        }
        if (t < 128) {
            swv6[t] = uu_w[(256 + t)*128 + 126];
            swv7[t] = uu_w[(256 + t)*128 + 127];
        }
        __syncthreads();
        if (t < 64) {
            int l = t >> 3, hh = t & 7;
            float A = 0.f, Bv = 0.f;
            #pragma unroll
            for (int d = 0; d < 16; d++) {
                float qv = sq[(l<<7) + (hh<<4) + d];
                A  += qv * uu_w[(128 + (hh<<4) + d)*128 + 126];
                Bv += qv * uu_w[(128 + (hh<<4) + d)*128 + 127];
            }
            sa[t] = A; sb[t] = Bv;
        }
        __syncthreads();

        // phase 1: scores, n = k4*128 + lane*4 + j
        float s[TLu][16];
        #pragma unroll
        for (int l = 0; l < TLu; l++)
            #pragma unroll
            for (int k = 0; k < 16; k++) s[l][k] = 0.f;
        const float* K0Th = g_K0T + (((b<<3) + h) << 4) * 512;
        #pragma unroll
        for (int d = 0; d < 16; d++) {
            float q0 = sq[((lw+0)<<7) + (h<<4) + d];
            float q1 = sq[((lw+1)<<7) + (h<<4) + d];
            float q2 = sq[((lw+2)<<7) + (h<<4) + d];
            float q3 = sq[((lw+3)<<7) + (h<<4) + d];
            const float* rp = K0Th + (d<<9) + (lane<<2);
            #pragma unroll
            for (int k4 = 0; k4 < 4; k4++) {
                float4 kv = *(const float4*)(rp + (k4<<7));
                s[0][4*k4+0]+=q0*kv.x; s[0][4*k4+1]+=q0*kv.y; s[0][4*k4+2]+=q0*kv.z; s[0][4*k4+3]+=q0*kv.w;
                s[1][4*k4+0]+=q1*kv.x; s[1][4*k4+1]+=q1*kv.y; s[1][4*k4+2]+=q1*kv.z; s[1][4*k4+3]+=q1*kv.w;
                s[2][4*k4+0]+=q2*kv.x; s[2][4*k4+1]+=q2*kv.y; s[2][4*k4+2]+=q2*kv.z; s[2][4*k4+3]+=q2*kv.w;
                s[3][4*k4+0]+=q3*kv.x; s[3][4*k4+1]+=q3*kv.y; s[3][4*k4+2]+=q3*kv.z; s[3][4*k4+3]+=q3*kv.w;
            }
        }

        // phase 2: ci correction + softmax + ci-weighted sums
        float rsum[TLu], rc0[TLu], rc1[TLu];
        #pragma unroll
        for (int l = 0; l < TLu; l++) {
            int lloc = lw + l;
            float av = sa[(lloc<<3) + h], bv = sb[(lloc<<3) + h];
            float m = -1e30f;
            #pragma unroll
            for (int k4 = 0; k4 < 4; k4++) {
                float4 c0 = *(const float4*)&sci0[(lloc<<9) + (k4<<7) + (lane<<2)];
                float4 c1 = *(const float4*)&sci1[(lloc<<9) + (k4<<7) + (lane<<2)];
                float* sp = &s[l][k4<<2];
                sp[0] = (sp[0] + c0.x*av + c1.x*bv) * 0.25f;
                sp[1] = (sp[1] + c0.y*av + c1.y*bv) * 0.25f;
                sp[2] = (sp[2] + c0.z*av + c1.z*bv) * 0.25f;
                sp[3] = (sp[3] + c0.w*av + c1.w*bv) * 0.25f;
                m = fmaxf(m, fmaxf(fmaxf(sp[0], sp[1]), fmaxf(sp[2], sp[3])));
            }
            #pragma unroll
            for (int o = 16; o > 0; o >>= 1) m = fmaxf(m, __shfl_xor_sync(0xffffffffu, m, o));
            float su = 0.f, cs0 = 0.f, cs1 = 0.f;
            #pragma unroll
            for (int k4 = 0; k4 < 4; k4++) {
                float4 c0 = *(const float4*)&sci0[(lloc<<9) + (k4<<7) + (lane<<2)];
                float4 c1 = *(const float4*)&sci1[(lloc<<9) + (k4<<7) + (lane<<2)];
                float* sp = &s[l][k4<<2];
                float e0 = __expf(sp[0]-m), e1 = __expf(sp[1]-m);
                float e2 = __expf(sp[2]-m), e3 = __expf(sp[3]-m);
                sp[0]=e0; sp[1]=e1; sp[2]=e2; sp[3]=e3;
                su  += (e0+e1) + (e2+e3);
                cs0 += e0*c0.x + e1*c0.y + e2*c0.z + e3*c0.w;
                cs1 += e0*c1.x + e1*c1.y + e2*c1.z + e3*c1.w;
            }
            #pragma unroll
            for (int o = 16; o > 0; o >>= 1) {
                su  += __shfl_xor_sync(0xffffffffu, su,  o);
                cs0 += __shfl_xor_sync(0xffffffffu, cs0, o);
                cs1 += __shfl_xor_sync(0xffffffffu, cs1, o);
            }
            rsum[l] = su; rc0[l] = cs0; rc1[l] = cs1;
        }

        // phase 3: P @ V0 + rank-2 V correction
        const float* V0Th = g_V0T + (((b<<3) + h) << 4) * 512;
        #pragma unroll
        for (int half = 0; half < 2; half++) {
            float acc[TLu][8];
            #pragma unroll
            for (int l = 0; l < TLu; l++)
                #pragma unroll
                for (int dd = 0; dd < 8; dd++) acc[l][dd] = 0.f;
            #pragma unroll
            for (int dd = 0; dd < 8; dd++) {
                const float* vp = V0Th + (((half<<3)+dd)<<9) + (lane<<2);
                #pragma unroll
                for (int k4 = 0; k4 < 4; k4++) {
                    float4 v4 = *(const float4*)(vp + (k4<<7));
                    #pragma unroll
                    for (int l = 0; l < TLu; l++) {
                        float* sp = &s[l][k4<<2];
                        acc[l][dd] += sp[0]*v4.x + sp[1]*v4.y + sp[2]*v4.z + sp[3]*v4.w;
                    }
                }
            }
            #pragma unroll
            for (int o = 16; o > 0; o >>= 1)
                #pragma unroll
                for (int l = 0; l < TLu; l++)
                    #pragma unroll
                    for (int dd = 0; dd < 8; dd++)
                        acc[l][dd] += __shfl_xor_sync(0xffffffffu, acc[l][dd], o);
            if (lane < 8) {
                int d = (half<<3) + lane;
                #pragma unroll
                for (int l = 0; l < TLu; l++) {
                    float av = pick8(acc[l], lane);
                    float ov = (av + rc0[l]*swv6[(h<<4)+d] + rc1[l]*swv7[(h<<4)+d]) / rsum[l];
                    g_att_u[((b*LL + l0 + lw + l) << 7) + (h<<4) + d] = ov;
                }
            }
        }
    } else {
        // -------- standard MHA (ta: z==1, du: z==2) --------
        int l0 = blockIdx.x * 4;
        int h  = w;
        const float* Q  = (z==1) ? g_qt  : g_qd;
        const float* KT = (z==1) ? g_ktT : g_kdT;
        const float* VT = (z==1) ? g_vtT : g_vdT;
        float* O        = (z==1) ? g_att_t : g_att_d;

        const float4* q4p = (const float4*)(Q + ((b*LL + l0) << 7));
        for (int i = t; i < 128; i += 256) ((float4*)sq)[i] = q4p[i];
        __syncthreads();

        float s[TLu][8];
        #pragma unroll
        for (int l = 0; l < TLu; l++)
            #pragma unroll
            for (int k = 0; k < 8; k++) s[l][k] = 0.f;
        const float* KTh = KT + (((b<<3) + h) << 4) * 256;
        #pragma unroll
        for (int d = 0; d < 16; d++) {
            float q0 = sq[(0<<7) + (h<<4) + d];
            float q1 = sq[(1<<7) + (h<<4) + d];
            float q2 = sq[(2<<7) + (h<<4) + d];
            float q3 = sq[(3<<7) + (h<<4) + d];
            const float* rp = KTh + (d<<8) + (lane<<2);
            #pragma unroll
            for (int k4 = 0; k4 < 2; k4++) {
                float4 kv = *(const float4*)(rp + (k4<<7));
                s[0][4*k4+0]+=q0*kv.x; s[0][4*k4+1]+=q0*kv.y; s[0][4*k4+2]+=q0*kv.z; s[0][4*k4+3]+=q0*kv.w;
                s[1][4*k4+0]+=q1*kv.x; s[1][4*k4+1]+=q1*kv.y; s[1][4*k4+2]+=q1*kv.z; s[1][4*k4+3]+=q1*kv.w;
                s[2][4*k4+0]+=q2*kv.x; s[2][4*k4+1]+=q2*kv.y; s[2][4*k4+2]+=q2*kv.z; s[2][4*k4+3]+=q2*kv.w;
                s[3][4*k4+0]+=q3*kv.x; s[3][4*k4+1]+=q3*kv.y; s[3][4*k4+2]+=q3*kv.z; s[3][4*k4+3]+=q3*kv.w;
            }
        }
        float rsum[TLu];
        #pragma unroll
        for (int l = 0; l < TLu; l++) {
            float m = -1e30f;
            #pragma unroll
            for (int k = 0; k < 8; k++) { s[l][k] *= 0.25f; m = fmaxf(m, s[l][k]); }
            #pragma unroll
            for (int o = 16; o > 0; o >>= 1) m = fmaxf(m, __shfl_xor_sync(0xffffffffu, m, o));
            float su = 0.f;
            #pragma unroll
            for (int k = 0; k < 8; k++) { float e = __expf(s[l][k]-m); s[l][k] = e; su += e; }
            #pragma unroll
            for (int o = 16; o > 0; o >>= 1) su += __shfl_xor_sync(0xffffffffu, su, o);
            rsum[l] = su;
        }
        const float* VTh = VT + (((b<<3) + h) << 4) * 256;
        #pragma unroll
        for (int half = 0; half < 2; half++) {
            float acc[TLu][8];
            #pragma unroll
            for (int l = 0; l < TLu; l++)
                #pragma unroll
                for (int dd = 0; dd < 8; dd++) acc[l][dd] = 0.f;
            #pragma unroll
            for (int dd = 0; dd < 8; dd++) {
                const float* vp = VTh + (((half<<3)+dd)<<8) + (lane<<2);
                #pragma unroll
                for (int k4 = 0; k4 < 2; k4++) {
                    float4 v4 = *(const float4*)(vp + (k4<<7));
                    #pragma unroll
                    for (int l = 0; l < TLu; l++) {
                        float* sp = &s[l][k4<<2];
                        acc[l][dd] += sp[0]*v4.x + sp[1]*v4.y + sp[2]*v4.z + sp[3]*v4.w;
                    }
                }
            }
            #pragma unroll
            for (int o = 16; o > 0; o >>= 1)
                #pragma unroll
                for (int l = 0; l < TLu; l++)
                    #pragma unroll
                    for (int dd = 0; dd < 8; dd++)
                        acc[l][dd] += __shfl_xor_sync(0xffffffffu, acc[l][dd], o);
            if (lane < 8) {
                int d = (half<<3) + lane;
                #pragma unroll
                for (int l = 0; l < TLu; l++) {
                    float av = pick8(acc[l], lane);
                    O[((b*LL + l0 + l) << 7) + (h<<4) + d] = av / rsum[l];
                }
            }
        }
    }
}

// ---------------- final partial GEMM: part_s = att_s @ M_s^T --------------
__global__ __launch_bounds__(256) void final_gemm_kernel() {
    __shared__ float As[32*33];
    __shared__ float Ws[32*132];
    int sidx = blockIdx.y;
    const float* A = (sidx==0) ? g_att_u : (sidx==1) ? g_att_t : g_att_d;
    const float* W = (sidx==0) ? g_Mu   : (sidx==1) ? g_Mt   : g_Md;
    float* P = g_part + sidx * (BLr*EE);
    int row0 = blockIdx.x << 5;
    int t = threadIdx.x;
    int ti = t >> 5, tj = t & 31;
    float acc[4][4] = {};
    for (int kc = 0; kc < 128; kc += 32) {
        #pragma unroll
        for (int i = 0; i < 4; i++) {
            int idx = t + i*256; int r = idx>>5, c = idx&31;
            As[r*33 + c] = A[(row0 + r)*128 + kc + c];
        }
        #pragma unroll
        for (int i = 0; i < 16; i++) {
            int idx = t + i*256; int col = idx>>5, kk = idx&31;
            Ws[kk*132 + col] = W[col*128 + kc + kk];
        }
        __syncthreads();
        #pragma unroll
        for (int kk = 0; kk < 32; kk++) {
            float4 w4 = *(const float4*)&Ws[kk*132 + (tj<<2)];
            #pragma unroll
            for (int i = 0; i < 4; i++) {
                float a = As[(ti*4+i)*33 + kk];
                acc[i][0] += a*w4.x; acc[i][1] += a*w4.y;
                acc[i][2] += a*w4.z; acc[i][3] += a*w4.w;
            }
        }
        __syncthreads();
    }
    #pragma unroll
    for (int i = 0; i < 4; i++) {
        int r = row0 + ti*4 + i;
        float4 o;
        o.x = acc[i][0]; o.y = acc[i][1]; o.z = acc[i][2]; o.w = acc[i][3];
        *(float4*)&P[r*128 + (tj<<2)] = o;
    }
}

// ---------------- fused BatchNorm (stats + apply + ReLU) ------------------
// Per-channel bias constants cancel in (y - mean): omitted entirely.
__global__ __launch_bounds__(256) void bn_fused_kernel(
    const float* __restrict__ gamma, const float* __restrict__ beta,
    float* __restrict__ out)
{
    __shared__ float red[256];
    int c = blockIdx.x, t = threadIdx.x;
    float s = 0.f;
    for (int i = t; i < 1024; i += 256) {
        float v = g_part[i*128 + c] + g_part[131072 + i*128 + c] + g_part[262144 + i*128 + c];
        g_y[i*128 + c] = v;
        s += v;
    }
    red[t] = s; __syncthreads();
    for (int o = 128; o > 0; o >>= 1) { if (t < o) red[t] += red[t+o]; __syncthreads(); }
    float mean = red[0] * (1.f/1024.f);
    __syncthreads();
    float vv = 0.f;
    for (int i = t; i < 1024; i += 256) { float d = g_y[i*128 + c] - mean; vv += d*d; }
    red[t] = vv; __syncthreads();
    for (int o = 128; o > 0; o >>= 1) { if (t < o) red[t] += red[t+o]; __syncthreads(); }
    float istd = rsqrtf(red[0] * (1.f/1024.f) + 1e-5f);
    float ga = gamma[c], be = beta[c];
    for (int i = t; i < 1024; i += 256) {
        float v = (g_y[i*128 + c] - mean) * istd * ga + be;
        out[i*128 + c] = fmaxf(v, 0.f);
    }
}

// ---------------- host launch --------------------------------------------
extern "C" void kernel_launch(void* const* d_in, const int* in_sizes, int n_in,
                              void* d_out, int out_size) {
    const float* UU    = (const float*)d_in[0];
    const float* DU    = (const float*)d_in[1];
    const float* TA    = (const float*)d_in[2];
    const float* CI    = (const float*)d_in[3];
    const float* uu_w  = (const float*)d_in[4];
    const float* uu_b  = (const float*)d_in[5];
    const float* uu_ow = (const float*)d_in[6];
    const float* ta_w  = (const float*)d_in[8];
    const float* ta_b  = (const float*)d_in[9];
    const float* ta_ow = (const float*)d_in[10];
    const float* du_w  = (const float*)d_in[12];
    const float* du_b  = (const float*)d_in[13];
    const float* du_ow = (const float*)d_in[14];
    const float* dim_w = (const float*)d_in[16];
    const float* gamma = (const float*)d_in[18];
    const float* beta  = (const float*)d_in[19];
    float* out = (float*)d_out;

    transpose_ci_kernel<<<dim3(16,16,4), dim3(32,8)>>>(CI);
    proj_all_kernel<<<dim3(32,12), 256>>>(DU, TA, UU, uu_w, uu_b, ta_w, ta_b,
                                          du_w, du_b, uu_ow, ta_ow, du_ow, dim_w);
    attn_kernel<<<dim3(64,4,3), 256>>>(uu_w);
    final_gemm_kernel<<<dim3(32,3), 256>>>();
    bn_fused_kernel<<<128,256>>>(gamma, beta, out);
}